// round 6
// baseline (speedup 1.0000x reference)
#include <cuda_runtime.h>
#include <cstdint>

// Problem: B=32, C=8, H=256, W=256 -> 256 maps of 65536 floats, 2 tensors.
#define NMAPS    256
#define GRID     592            // 148 SMs x exactly 4 CTAs
#define NTHR     256
#define TILE_F4  1024           // float4s per tensor per tile (4096 floats = 1/16 map)
#define NTILES   4096           // 4,194,304 f4 / 1024
#define TPM      16             // tiles per map
#define CHUNK_F4 256            // 1 float4 per thread per tensor per chunk
#define NSTAGES  4

// Per-tile partials (no allocation: __device__ globals).
__device__ float        g_s [NTILES];
__device__ float        g_sx[NTILES];
__device__ float        g_sy[NTILES];
__device__ float        g_m [NTILES];
__device__ int          g_i [NTILES];
__device__ unsigned int g_count = 0;

__device__ __forceinline__ void cp16(void* dst_smem, const float4* src) {
    uint32_t d = (uint32_t)__cvta_generic_to_shared(dst_smem);
    asm volatile("cp.async.cg.shared.global [%0], [%1], 16;\n" :: "r"(d), "l"(src));
}

__global__ __launch_bounds__(NTHR)
void dsnt_tile_kernel(const float* __restrict__ inp,
                      const float* __restrict__ tgt,
                      float* __restrict__ out) {
    __shared__ float4 smi[NSTAGES][CHUNK_F4];   // input stages  (16 KB)
    __shared__ float4 smt[NSTAGES][CHUNK_F4];   // target stages (16 KB)
    __shared__ float  sh_s [8], sh_sx[8], sh_sy[8], sh_m [8], sh_ed[8];
    __shared__ int    sh_i [8], sh_fl[1];

    const int blk = blockIdx.x;
    const int tid = threadIdx.x;
    const int lane = tid & 31;
    const int wid  = tid >> 5;
    const float4* __restrict__ in4 = (const float4*)inp;
    const float4* __restrict__ tg4 = (const float4*)tgt;

    // tiles for this CTA: blk, blk+GRID, ... ; chunk c -> tile blk+(c>>2)*GRID
    const int ntiles = (NTILES - blk + GRID - 1) / GRID;   // 6 or 7
    const int NC = 4 * ntiles;

    auto f4base = [&](int c) {
        int tile = blk + (c >> 2) * GRID;
        return tile * TILE_F4 + (c & 3) * CHUNK_F4 + tid;  // global float4 index
    };

    // ---- prologue: 3 groups ahead ----
    #pragma unroll
    for (int c = 0; c < NSTAGES - 1; ++c) {
        if (c < NC) {
            int b = f4base(c);
            cp16(&smi[c][tid], in4 + b);
            cp16(&smt[c][tid], tg4 + b);
        }
        asm volatile("cp.async.commit_group;\n" ::: "memory");
    }

    float s = 0.f, sx = 0.f, sy = 0.f;
    float tmax = -1e30f;
    int   ebest = 0;
    float wx = 0.f, wy = 0.f, wz = 0.f, ww = 0.f;
    const unsigned FULL = 0xFFFFFFFFu;

    #pragma unroll 4
    for (int c = 0; c < NC; ++c) {
        const int slot = c & 3;
        asm volatile("cp.async.wait_group %0;\n" :: "n"(NSTAGES - 2) : "memory");

        float4 a = smi[slot][tid];
        float4 t = smt[slot][tid];

        // refill chunk c+3 (thread-private slot, its prior LDS was issued last iter)
        int cn = c + NSTAGES - 1;
        if (cn < NC) {
            int b = f4base(cn);
            cp16(&smi[cn & 3][tid], in4 + b);
            cp16(&smt[cn & 3][tid], tg4 + b);
        }
        asm volatile("cp.async.commit_group;\n" ::: "memory");

        // ---- accumulate ----
        int e0  = (f4base(c) << 2) & 65535;     // element index within its map
        int col = e0 & 255;
        int row = e0 >> 8;
        float ex = __expf(a.x);
        float ey = __expf(a.y);
        float ez = __expf(a.z);
        float ew = __expf(a.w);
        float es = (ex + ey) + (ez + ew);
        s  += es;
        sy  = fmaf(es, (float)(row + 1), sy);
        float extra = fmaf(2.f, ez, ey);
        extra = fmaf(3.f, ew, extra);
        sx += fmaf(es, (float)(col + 1), extra);
        float v = fmaxf(fmaxf(t.x, t.y), fmaxf(t.z, t.w));
        if (v > tmax) { tmax = v; ebest = e0; wx = t.x; wy = t.y; wz = t.z; ww = t.w; }

        // ---- tile boundary: block-reduce, write per-tile partials ----
        if ((c & 3) == 3) {
            int cc = (wx == tmax) ? 0 : (wy == tmax) ? 1 : (wz == tmax) ? 2 : 3;
            int tidx = ebest + cc;
            #pragma unroll
            for (int o = 16; o > 0; o >>= 1) {
                s  += __shfl_down_sync(FULL, s,  o);
                sx += __shfl_down_sync(FULL, sx, o);
                sy += __shfl_down_sync(FULL, sy, o);
                float om = __shfl_down_sync(FULL, tmax, o);
                int   oi = __shfl_down_sync(FULL, tidx, o);
                if (om > tmax || (om == tmax && oi < tidx)) { tmax = om; tidx = oi; }
            }
            __syncthreads();                        // scratch safe to overwrite
            if (lane == 0) {
                sh_s [wid] = s;  sh_sx[wid] = sx;  sh_sy[wid] = sy;
                sh_m [wid] = tmax;  sh_i [wid] = tidx;
            }
            __syncthreads();
            if (tid == 0) {
                float S = sh_s[0], SX = sh_sx[0], SY = sh_sy[0];
                float M = sh_m[0];
                int   I = sh_i[0];
                #pragma unroll
                for (int w = 1; w < 8; ++w) {
                    S += sh_s[w];  SX += sh_sx[w];  SY += sh_sy[w];
                    float om = sh_m[w]; int oi = sh_i[w];
                    if (om > M || (om == M && oi < I)) { M = om; I = oi; }
                }
                int tile = blk + (c >> 2) * GRID;
                g_s [tile] = S;  g_sx[tile] = SX;  g_sy[tile] = SY;
                g_m [tile] = M;  g_i [tile] = I;
            }
            // reset accumulators for next tile
            s = sx = sy = 0.f;
            tmax = -1e30f; ebest = 0;
            wx = wy = wz = ww = 0.f;
        }
    }

    // ---- completion counting ----
    if (tid == 0) {
        __threadfence();
        unsigned int prev = atomicAdd(&g_count, 1u);
        sh_fl[0] = (prev == GRID - 1) ? 1 : 0;
    }
    __syncthreads();

    // ---- last CTA: fold 4096 tile partials -> 256 maps -> scalar ----
    if (sh_fl[0]) {
        __threadfence();                       // acquire all partials
        const int m = tid;                     // map index 0..255
        float S = 0.f, SX = 0.f, SY = 0.f;
        float M = -1e30f;
        int   I = 0x7FFFFFFF;
        #pragma unroll
        for (int q = 0; q < TPM; ++q) {        // ascending tiles: strict > keeps lowest index
            int tl = m * TPM + q;
            S  += g_s [tl];
            SX += g_sx[tl];
            SY += g_sy[tl];
            float om = g_m[tl];
            if (om > M) { M = om; I = g_i[tl]; }
        }
        float inv = 1.0f / (S * 256.0f);
        float px = SX * inv;
        float py = SY * inv;
        float tx = (float)((I & 255) + 1) * (1.0f / 256.0f);
        float ty = (float)((I >> 8)  + 1) * (1.0f / 256.0f);
        float dx = tx - px, dy = ty - py;
        float ed = sqrtf(dx * dx + dy * dy);

        #pragma unroll
        for (int o = 16; o > 0; o >>= 1) ed += __shfl_down_sync(FULL, ed, o);
        if (lane == 0) sh_ed[wid] = ed;
        __syncthreads();
        if (wid == 0) {
            ed = (lane < 8) ? sh_ed[lane] : 0.f;
            #pragma unroll
            for (int o = 4; o > 0; o >>= 1) ed += __shfl_down_sync(FULL, ed, o);
            if (lane == 0) {
                out[0] = ed * (1.0f / 32.0f);
                g_count = 0;                   // reset for next graph replay
            }
        }
    }
}

extern "C" void kernel_launch(void* const* d_in, const int* in_sizes, int n_in,
                              void* d_out, int out_size) {
    const float* inp = (const float*)d_in[0];
    const float* tgt = (const float*)d_in[1];
    dsnt_tile_kernel<<<GRID, NTHR>>>(inp, tgt, (float*)d_out);
}

// round 7
// speedup vs baseline: 1.1251x; 1.1251x over previous
#include <cuda_runtime.h>
#include <cstdint>

// Problem: B=32, C=8, H=256, W=256 -> 256 maps of 65536 floats, 2 tensors.
#define NMAPS    256
#define NBLK     1024          // 4 quarter-map CTAs per map, single balanced wave @7/SM
#define NTHR     256
#define QUART_F4 4096          // float4s per quarter-map
#define CHUNK_F4 256           // 1 float4 per thread per tensor per chunk
#define NCHUNK   16
#define NSTAGES  3             // 24 KB stage smem -> 7 CTAs/SM

// Per-quarter partials (no allocation: __device__ globals).
__device__ float        g_s [NBLK];
__device__ float        g_sx[NBLK];
__device__ float        g_sy[NBLK];
__device__ float        g_m [NBLK];
__device__ int          g_i [NBLK];
__device__ unsigned int g_count = 0;

__device__ __forceinline__ void cp16(void* dst_smem, const float4* src) {
    uint32_t d = (uint32_t)__cvta_generic_to_shared(dst_smem);
    asm volatile("cp.async.cg.shared.global [%0], [%1], 16;\n" :: "r"(d), "l"(src));
}

__global__ __launch_bounds__(NTHR, 7)
void dsnt_quarter_kernel(const float* __restrict__ inp,
                         const float* __restrict__ tgt,
                         float* __restrict__ out) {
    __shared__ float4 smi[NSTAGES][CHUNK_F4];   // 12 KB
    __shared__ float4 smt[NSTAGES][CHUNK_F4];   // 12 KB
    __shared__ float  sh_s [8], sh_sx[8], sh_sy[8], sh_m [8], sh_ed[8];
    __shared__ int    sh_i [8], sh_fl[1];

    const int blk = blockIdx.x;
    const int tid = threadIdx.x;
    const float4* __restrict__ in4 = (const float4*)inp + (size_t)blk * QUART_F4;
    const float4* __restrict__ tg4 = (const float4*)tgt + (size_t)blk * QUART_F4;
    const int ebase = (blk & 3) << 14;          // element offset within the map

    // ---- prologue: 2 groups ahead (thread-private slots) ----
    #pragma unroll
    for (int k = 0; k < NSTAGES - 1; ++k) {
        cp16(&smi[k][tid], in4 + k * CHUNK_F4 + tid);
        cp16(&smt[k][tid], tg4 + k * CHUNK_F4 + tid);
        asm volatile("cp.async.commit_group;\n" ::: "memory");
    }

    float s = 0.f, sx = 0.f, sy = 0.f;
    float tmax = -1e30f;
    int   ebest = 0;
    float wx = 0.f, wy = 0.f, wz = 0.f, ww = 0.f;

    #pragma unroll
    for (int k = 0; k < NCHUNK; ++k) {
        const int slot = k % NSTAGES;
        asm volatile("cp.async.wait_group %0;\n" :: "n"(NSTAGES - 2) : "memory");

        float4 a = smi[slot][tid];
        float4 t = smt[slot][tid];

        // refill this thread's slot for chunk k+2 (no barrier: private slot)
        const int kn = k + NSTAGES - 1;
        if (kn < NCHUNK) {
            const int sl = kn % NSTAGES;
            cp16(&smi[sl][tid], in4 + kn * CHUNK_F4 + tid);
            cp16(&smt[sl][tid], tg4 + kn * CHUNK_F4 + tid);
        }
        asm volatile("cp.async.commit_group;\n" ::: "memory");

        // ---- accumulate ----
        int e0  = ebase + ((k * CHUNK_F4 + tid) << 2);
        int col = e0 & 255;
        int row = e0 >> 8;
        float ex = __expf(a.x);
        float ey = __expf(a.y);
        float ez = __expf(a.z);
        float ew = __expf(a.w);
        float es = (ex + ey) + (ez + ew);
        s  += es;
        sy  = fmaf(es, (float)(row + 1), sy);
        float extra = fmaf(2.f, ez, ey);
        extra = fmaf(3.f, ew, extra);
        sx += fmaf(es, (float)(col + 1), extra);
        // tree max + single conditional keep; strict > + ascending e0 = first index
        float v = fmaxf(fmaxf(t.x, t.y), fmaxf(t.z, t.w));
        if (v > tmax) { tmax = v; ebest = e0; wx = t.x; wy = t.y; wz = t.z; ww = t.w; }
    }

    // reconstruct element index within the winning float4 (first match wins)
    int c = (wx == tmax) ? 0 : (wy == tmax) ? 1 : (wz == tmax) ? 2 : 3;
    int tidx = ebest + c;

    // ---- warp reduction ----
    const unsigned FULL = 0xFFFFFFFFu;
    #pragma unroll
    for (int o = 16; o > 0; o >>= 1) {
        s  += __shfl_down_sync(FULL, s,  o);
        sx += __shfl_down_sync(FULL, sx, o);
        sy += __shfl_down_sync(FULL, sy, o);
        float om = __shfl_down_sync(FULL, tmax, o);
        int   oi = __shfl_down_sync(FULL, tidx, o);
        if (om > tmax || (om == tmax && oi < tidx)) { tmax = om; tidx = oi; }
    }

    // ---- cross-warp reduction (8 warps) ----
    const int lane = tid & 31;
    const int wid  = tid >> 5;
    if (lane == 0) {
        sh_s [wid] = s;  sh_sx[wid] = sx;  sh_sy[wid] = sy;
        sh_m [wid] = tmax;  sh_i [wid] = tidx;
    }
    __syncthreads();

    if (wid == 0) {
        s    = (lane < 8) ? sh_s [lane] : 0.f;
        sx   = (lane < 8) ? sh_sx[lane] : 0.f;
        sy   = (lane < 8) ? sh_sy[lane] : 0.f;
        tmax = (lane < 8) ? sh_m [lane] : -1e30f;
        tidx = (lane < 8) ? sh_i [lane] : 0x7FFFFFFF;
        #pragma unroll
        for (int o = 4; o > 0; o >>= 1) {
            s  += __shfl_down_sync(FULL, s,  o);
            sx += __shfl_down_sync(FULL, sx, o);
            sy += __shfl_down_sync(FULL, sy, o);
            float om = __shfl_down_sync(FULL, tmax, o);
            int   oi = __shfl_down_sync(FULL, tidx, o);
            if (om > tmax || (om == tmax && oi < tidx)) { tmax = om; tidx = oi; }
        }
        if (lane == 0) {
            g_s [blk] = s;  g_sx[blk] = sx;  g_sy[blk] = sy;
            g_m [blk] = tmax;  g_i [blk] = tidx;
            __threadfence();
            unsigned int prev = atomicAdd(&g_count, 1u);
            sh_fl[0] = (prev == NBLK - 1) ? 1 : 0;
        }
    }
    __syncthreads();

    // ---- last CTA: fold 1024 quarter partials -> 256 maps -> scalar ----
    if (sh_fl[0]) {
        __threadfence();                       // acquire all partials
        const int m = tid;                     // map index 0..255
        float S = 0.f, SX = 0.f, SY = 0.f;
        float M = -1e30f;
        int   I = 0x7FFFFFFF;
        #pragma unroll
        for (int q = 0; q < 4; ++q) {          // ascending quarters: strict > keeps lowest index
            int b = 4 * m + q;
            S  += g_s [b];
            SX += g_sx[b];
            SY += g_sy[b];
            float om = g_m[b];
            if (om > M) { M = om; I = g_i[b]; }
        }
        float inv = 1.0f / (S * 256.0f);
        float px = SX * inv;
        float py = SY * inv;
        float tx = (float)((I & 255) + 1) * (1.0f / 256.0f);
        float ty = (float)((I >> 8)  + 1) * (1.0f / 256.0f);
        float dx = tx - px, dy = ty - py;
        float ed = sqrtf(dx * dx + dy * dy);

        #pragma unroll
        for (int o = 16; o > 0; o >>= 1) ed += __shfl_down_sync(FULL, ed, o);
        if (lane == 0) sh_ed[wid] = ed;
        __syncthreads();
        if (wid == 0) {
            ed = (lane < 8) ? sh_ed[lane] : 0.f;
            #pragma unroll
            for (int o = 4; o > 0; o >>= 1) ed += __shfl_down_sync(FULL, ed, o);
            if (lane == 0) {
                out[0] = ed * (1.0f / 32.0f);
                g_count = 0;                   // reset for next graph replay
            }
        }
    }
}

extern "C" void kernel_launch(void* const* d_in, const int* in_sizes, int n_in,
                              void* d_out, int out_size) {
    const float* inp = (const float*)d_in[0];
    const float* tgt = (const float*)d_in[1];
    dsnt_quarter_kernel<<<NBLK, NTHR>>>(inp, tgt, (float*)d_out);
}

// round 8
// speedup vs baseline: 1.1764x; 1.0456x over previous
#include <cuda_runtime.h>
#include <cstdint>

// Problem: B=32, C=8, H=256, W=256 -> 256 maps of 65536 floats, 2 tensors.
#define NMAPS     256
#define NBLK      512          // 2 half-map CTAs per map (best shape so far)
#define NTHR      256
#define HALF_F4   8192         // float4s per half-map per tensor
#define CHUNK_F4  256          // 1 float4 per thread per tensor per chunk (4 KB)
#define NCHUNK    32
#define NSTAGES   5            // 5 x 8 KB stage smem = 40 KB (static)
#define CHUNK_BYTES (CHUNK_F4 * 16)   // 4096 per tensor

// Per-half-map partials (no allocation: __device__ globals).
__device__ float        g_s [NBLK];
__device__ float        g_sx[NBLK];
__device__ float        g_sy[NBLK];
__device__ float        g_m [NBLK];
__device__ int          g_i [NBLK];
__device__ unsigned int g_count = 0;

__device__ __forceinline__ uint32_t s2u(const void* p) {
    return (uint32_t)__cvta_generic_to_shared(p);
}

__device__ __forceinline__ void bulk_cp(uint32_t dst, const void* gsrc,
                                        uint32_t bytes, uint32_t mbar) {
    asm volatile(
        "cp.async.bulk.shared::cta.global.mbarrier::complete_tx::bytes [%0], [%1], %2, [%3];"
        :: "r"(dst), "l"(gsrc), "r"(bytes), "r"(mbar) : "memory");
}

__device__ __forceinline__ void mbar_init(uint32_t mbar, uint32_t cnt) {
    asm volatile("mbarrier.init.shared.b64 [%0], %1;" :: "r"(mbar), "r"(cnt) : "memory");
}

__device__ __forceinline__ void mbar_expect_tx(uint32_t mbar, uint32_t bytes) {
    asm volatile("mbarrier.arrive.expect_tx.shared.b64 _, [%0], %1;"
                 :: "r"(mbar), "r"(bytes) : "memory");
}

__device__ __forceinline__ void mbar_wait(uint32_t mbar, uint32_t parity) {
    asm volatile(
        "{\n\t"
        ".reg .pred P1;\n\t"
        "WAIT_LOOP_%=:\n\t"
        "mbarrier.try_wait.parity.acquire.cta.shared::cta.b64 P1, [%0], %1, 0x989680;\n\t"
        "@P1 bra.uni WAIT_DONE_%=;\n\t"
        "bra.uni WAIT_LOOP_%=;\n\t"
        "WAIT_DONE_%=:\n\t"
        "}"
        :: "r"(mbar), "r"(parity) : "memory");
}

__global__ __launch_bounds__(NTHR)
void dsnt_bulk_kernel(const float* __restrict__ inp,
                      const float* __restrict__ tgt,
                      float* __restrict__ out) {
    __shared__ float4 smi[NSTAGES][CHUNK_F4];        // 20 KB
    __shared__ float4 smt[NSTAGES][CHUNK_F4];        // 20 KB
    __shared__ alignas(8) unsigned long long mbar_full[NSTAGES];
    __shared__ float  sh_s [8], sh_sx[8], sh_sy[8], sh_m [8], sh_ed[8];
    __shared__ int    sh_i [8], sh_fl[1];

    const int blk = blockIdx.x;
    const int tid = threadIdx.x;
    const float* __restrict__ inb = inp + (size_t)blk * (HALF_F4 * 4);
    const float* __restrict__ tgb = tgt + (size_t)blk * (HALF_F4 * 4);
    const int ebase = (blk & 1) << 15;               // element offset within map

    // ---- init barriers, issue NSTAGES-1 chunks ahead ----
    if (tid == 0) {
        #pragma unroll
        for (int sN = 0; sN < NSTAGES; ++sN) mbar_init(s2u(&mbar_full[sN]), 1);
        // make inits visible to the bulk-async proxy before first copy
        asm volatile("fence.proxy.async.shared::cta;" ::: "memory");
        #pragma unroll
        for (int k = 0; k < NSTAGES - 1; ++k) {
            uint32_t mb = s2u(&mbar_full[k]);
            mbar_expect_tx(mb, 2 * CHUNK_BYTES);
            bulk_cp(s2u(&smi[k][0]), inb + k * (CHUNK_F4 * 4), CHUNK_BYTES, mb);
            bulk_cp(s2u(&smt[k][0]), tgb + k * (CHUNK_F4 * 4), CHUNK_BYTES, mb);
        }
    }
    __syncthreads();

    float s = 0.f, sx = 0.f, sy = 0.f;
    float tmax = -1e30f;
    int   ebest = 0;
    float wx = 0.f, wy = 0.f, wz = 0.f, ww = 0.f;

    for (int k = 0; k < NCHUNK; ++k) {
        const int slot = k % NSTAGES;
        const uint32_t parity = (uint32_t)((k / NSTAGES) & 1);
        mbar_wait(s2u(&mbar_full[slot]), parity);

        float4 a = smi[slot][tid];
        float4 t = smt[slot][tid];

        // ---- accumulate ----
        int e0  = ebase + ((k * CHUNK_F4 + tid) << 2);
        int col = e0 & 255;
        int row = e0 >> 8;
        float ex = __expf(a.x);
        float ey = __expf(a.y);
        float ez = __expf(a.z);
        float ew = __expf(a.w);
        float es = (ex + ey) + (ez + ew);
        s  += es;
        sy  = fmaf(es, (float)(row + 1), sy);
        float extra = fmaf(2.f, ez, ey);
        extra = fmaf(3.f, ew, extra);
        sx += fmaf(es, (float)(col + 1), extra);
        float v = fmaxf(fmaxf(t.x, t.y), fmaxf(t.z, t.w));
        if (v > tmax) { tmax = v; ebest = e0; wx = t.x; wy = t.y; wz = t.z; ww = t.w; }

        // all threads done with this chunk -> stage (k+NSTAGES-1)%NSTAGES
        // (= stage of chunk k-1, already consumed) is free to refill
        __syncthreads();
        const int kn = k + NSTAGES - 1;
        if (tid == 0 && kn < NCHUNK) {
            const int sl = kn % NSTAGES;
            uint32_t mb = s2u(&mbar_full[sl]);
            mbar_expect_tx(mb, 2 * CHUNK_BYTES);
            bulk_cp(s2u(&smi[sl][0]), inb + kn * (CHUNK_F4 * 4), CHUNK_BYTES, mb);
            bulk_cp(s2u(&smt[sl][0]), tgb + kn * (CHUNK_F4 * 4), CHUNK_BYTES, mb);
        }
    }

    // reconstruct element index within the winning float4 (first match wins)
    int c = (wx == tmax) ? 0 : (wy == tmax) ? 1 : (wz == tmax) ? 2 : 3;
    int tidx = ebest + c;

    // ---- warp reduction ----
    const unsigned FULL = 0xFFFFFFFFu;
    #pragma unroll
    for (int o = 16; o > 0; o >>= 1) {
        s  += __shfl_down_sync(FULL, s,  o);
        sx += __shfl_down_sync(FULL, sx, o);
        sy += __shfl_down_sync(FULL, sy, o);
        float om = __shfl_down_sync(FULL, tmax, o);
        int   oi = __shfl_down_sync(FULL, tidx, o);
        if (om > tmax || (om == tmax && oi < tidx)) { tmax = om; tidx = oi; }
    }

    // ---- cross-warp reduction (8 warps) ----
    const int lane = tid & 31;
    const int wid  = tid >> 5;
    if (lane == 0) {
        sh_s [wid] = s;  sh_sx[wid] = sx;  sh_sy[wid] = sy;
        sh_m [wid] = tmax;  sh_i [wid] = tidx;
    }
    __syncthreads();

    if (wid == 0) {
        s    = (lane < 8) ? sh_s [lane] : 0.f;
        sx   = (lane < 8) ? sh_sx[lane] : 0.f;
        sy   = (lane < 8) ? sh_sy[lane] : 0.f;
        tmax = (lane < 8) ? sh_m [lane] : -1e30f;
        tidx = (lane < 8) ? sh_i [lane] : 0x7FFFFFFF;
        #pragma unroll
        for (int o = 4; o > 0; o >>= 1) {
            s  += __shfl_down_sync(FULL, s,  o);
            sx += __shfl_down_sync(FULL, sx, o);
            sy += __shfl_down_sync(FULL, sy, o);
            float om = __shfl_down_sync(FULL, tmax, o);
            int   oi = __shfl_down_sync(FULL, tidx, o);
            if (om > tmax || (om == tmax && oi < tidx)) { tmax = om; tidx = oi; }
        }
        if (lane == 0) {
            g_s [blk] = s;  g_sx[blk] = sx;  g_sy[blk] = sy;
            g_m [blk] = tmax;  g_i [blk] = tidx;
            __threadfence();
            unsigned int prev = atomicAdd(&g_count, 1u);
            sh_fl[0] = (prev == NBLK - 1) ? 1 : 0;
        }
    }
    __syncthreads();

    // ---- last CTA: combine 512 partials -> 256 distances -> scalar ----
    if (sh_fl[0]) {
        __threadfence();                   // acquire all partials
        const int m = tid;                 // map index 0..255
        float s0  = g_s [2*m],   s1  = g_s [2*m+1];
        float sx0 = g_sx[2*m],   sx1 = g_sx[2*m+1];
        float sy0 = g_sy[2*m],   sy1 = g_sy[2*m+1];
        float m0  = g_m [2*m],   m1  = g_m [2*m+1];
        int   i0  = g_i [2*m],   i1  = g_i [2*m+1];

        float S  = s0 + s1;
        float SX = sx0 + sx1;
        float SY = sy0 + sy1;
        int   I  = (m1 > m0) ? i1 : i0;    // first half has lower indices

        float inv = 1.0f / (S * 256.0f);
        float px = SX * inv;
        float py = SY * inv;
        float tx = (float)((I & 255) + 1) * (1.0f / 256.0f);
        float ty = (float)((I >> 8)  + 1) * (1.0f / 256.0f);
        float dx = tx - px, dy = ty - py;
        float ed = sqrtf(dx * dx + dy * dy);

        #pragma unroll
        for (int o = 16; o > 0; o >>= 1) ed += __shfl_down_sync(FULL, ed, o);
        if (lane == 0) sh_ed[wid] = ed;
        __syncthreads();
        if (wid == 0) {
            ed = (lane < 8) ? sh_ed[lane] : 0.f;
            #pragma unroll
            for (int o = 4; o > 0; o >>= 1) ed += __shfl_down_sync(FULL, ed, o);
            if (lane == 0) {
                out[0] = ed * (1.0f / 32.0f);
                g_count = 0;               // reset for next graph replay
            }
        }
    }
}

extern "C" void kernel_launch(void* const* d_in, const int* in_sizes, int n_in,
                              void* d_out, int out_size) {
    const float* inp = (const float*)d_in[0];
    const float* tgt = (const float*)d_in[1];
    dsnt_bulk_kernel<<<NBLK, NTHR>>>(inp, tgt, (float*)d_out);
}

// round 9
// speedup vs baseline: 1.5351x; 1.3049x over previous
#include <cuda_runtime.h>
#include <cstdint>

// Problem: B=32, C=8, H=256, W=256 -> 256 maps of 65536 floats, 2 tensors.
#define NMAPS    256
#define NBLK     512          // 2 half-map CTAs per map
#define NTHR     256
#define HALF_F4  8192         // float4s per half-map per tensor

// Per-half-map partials (no allocation: __device__ globals).
__device__ float        g_s [NBLK];
__device__ float        g_sx[NBLK];
__device__ float        g_sy[NBLK];
__device__ float        g_m [NBLK];
__device__ int          g_i [NBLK];
__device__ unsigned int g_count = 0;

// Hinted vector load: read-only (nc) with an L2 cache policy operand.
__device__ __forceinline__ float4 ldg_pol(const float4* p, unsigned long long pol) {
    float4 v;
    asm volatile("ld.global.nc.L2::cache_hint.v4.f32 {%0,%1,%2,%3}, [%4], %5;"
                 : "=f"(v.x), "=f"(v.y), "=f"(v.z), "=f"(v.w)
                 : "l"(p), "l"(pol));
    return v;
}

__device__ __forceinline__ void accum4(float4 a, float4 t, int e0,
                                       float& s, float& sx, float& sy,
                                       float& tmax, int& ebest,
                                       float& wx, float& wy, float& wz, float& ww) {
    int col = e0 & 255;
    int row = e0 >> 8;
    float ex = __expf(a.x);
    float ey = __expf(a.y);
    float ez = __expf(a.z);
    float ew = __expf(a.w);
    float es = (ex + ey) + (ez + ew);
    s  += es;
    sy  = fmaf(es, (float)(row + 1), sy);
    float extra = fmaf(2.f, ez, ey);
    extra = fmaf(3.f, ew, extra);
    sx += fmaf(es, (float)(col + 1), extra);
    // tree max + single conditional keep; strict > + ascending e0 = first index
    float v = fmaxf(fmaxf(t.x, t.y), fmaxf(t.z, t.w));
    if (v > tmax) { tmax = v; ebest = e0; wx = t.x; wy = t.y; wz = t.z; ww = t.w; }
}

__global__ __launch_bounds__(NTHR)
void dsnt_l2pin_kernel(const float* __restrict__ inp,
                       const float* __restrict__ tgt,
                       float* __restrict__ out) {
    __shared__ float sh_s [8], sh_sx[8], sh_sy[8], sh_m [8], sh_ed[8];
    __shared__ int   sh_i [8], sh_fl[1];

    const int blk = blockIdx.x;
    const int tid = threadIdx.x;
    const float4* __restrict__ in4 = (const float4*)inp + (size_t)blk * HALF_F4;
    const float4* __restrict__ tg4 = (const float4*)tgt + (size_t)blk * HALF_F4;
    const int ebase = (blk & 1) << 15;          // element offset within the map

    // L2 policies: input persists (evict_last), target streams (evict_first).
    unsigned long long pol_keep, pol_stream;
    asm volatile("createpolicy.fractional.L2::evict_last.b64 %0, 1.0;"  : "=l"(pol_keep));
    asm volatile("createpolicy.fractional.L2::evict_first.b64 %0, 1.0;" : "=l"(pol_stream));

    float s = 0.f, sx = 0.f, sy = 0.f;
    float tmax = -1e30f;
    int   ebest = 0;
    float wx = 0.f, wy = 0.f, wz = 0.f, ww = 0.f;

    // 8192 f4 / 256 threads = 32 slots; 16 iterations x 2 slots, 4 loads batched.
    #pragma unroll 4
    for (int it = 0; it < 16; ++it) {
        int j0 = tid + it * (2 * NTHR);
        int j1 = j0 + NTHR;
        float4 a0 = ldg_pol(in4 + j0, pol_keep);
        float4 t0 = ldg_pol(tg4 + j0, pol_stream);
        float4 a1 = ldg_pol(in4 + j1, pol_keep);
        float4 t1 = ldg_pol(tg4 + j1, pol_stream);
        accum4(a0, t0, ebase + (j0 << 2), s, sx, sy, tmax, ebest, wx, wy, wz, ww);
        accum4(a1, t1, ebase + (j1 << 2), s, sx, sy, tmax, ebest, wx, wy, wz, ww);
    }

    // reconstruct element index within the winning float4 (first match wins)
    int c = (wx == tmax) ? 0 : (wy == tmax) ? 1 : (wz == tmax) ? 2 : 3;
    int tidx = ebest + c;

    // ---- warp reduction ----
    const unsigned FULL = 0xFFFFFFFFu;
    #pragma unroll
    for (int o = 16; o > 0; o >>= 1) {
        s  += __shfl_down_sync(FULL, s,  o);
        sx += __shfl_down_sync(FULL, sx, o);
        sy += __shfl_down_sync(FULL, sy, o);
        float om = __shfl_down_sync(FULL, tmax, o);
        int   oi = __shfl_down_sync(FULL, tidx, o);
        if (om > tmax || (om == tmax && oi < tidx)) { tmax = om; tidx = oi; }
    }

    // ---- cross-warp reduction (8 warps) ----
    const int lane = tid & 31;
    const int wid  = tid >> 5;
    if (lane == 0) {
        sh_s [wid] = s;  sh_sx[wid] = sx;  sh_sy[wid] = sy;
        sh_m [wid] = tmax;  sh_i [wid] = tidx;
    }
    __syncthreads();

    if (wid == 0) {
        s    = (lane < 8) ? sh_s [lane] : 0.f;
        sx   = (lane < 8) ? sh_sx[lane] : 0.f;
        sy   = (lane < 8) ? sh_sy[lane] : 0.f;
        tmax = (lane < 8) ? sh_m [lane] : -1e30f;
        tidx = (lane < 8) ? sh_i [lane] : 0x7FFFFFFF;
        #pragma unroll
        for (int o = 4; o > 0; o >>= 1) {
            s  += __shfl_down_sync(FULL, s,  o);
            sx += __shfl_down_sync(FULL, sx, o);
            sy += __shfl_down_sync(FULL, sy, o);
            float om = __shfl_down_sync(FULL, tmax, o);
            int   oi = __shfl_down_sync(FULL, tidx, o);
            if (om > tmax || (om == tmax && oi < tidx)) { tmax = om; tidx = oi; }
        }
        if (lane == 0) {
            g_s [blk] = s;  g_sx[blk] = sx;  g_sy[blk] = sy;
            g_m [blk] = tmax;  g_i [blk] = tidx;
            __threadfence();
            unsigned int prev = atomicAdd(&g_count, 1u);
            sh_fl[0] = (prev == NBLK - 1) ? 1 : 0;
        }
    }
    __syncthreads();

    // ---- last CTA: combine 512 partials -> 256 distances -> scalar ----
    if (sh_fl[0]) {
        __threadfence();                   // acquire all partials
        const int m = tid;                 // map index 0..255
        float s0  = g_s [2*m],   s1  = g_s [2*m+1];
        float sx0 = g_sx[2*m],   sx1 = g_sx[2*m+1];
        float sy0 = g_sy[2*m],   sy1 = g_sy[2*m+1];
        float m0  = g_m [2*m],   m1  = g_m [2*m+1];
        int   i0  = g_i [2*m],   i1  = g_i [2*m+1];

        float S  = s0 + s1;
        float SX = sx0 + sx1;
        float SY = sy0 + sy1;
        int   I  = (m1 > m0) ? i1 : i0;    // first half has lower indices

        float inv = 1.0f / (S * 256.0f);
        float px = SX * inv;
        float py = SY * inv;
        float tx = (float)((I & 255) + 1) * (1.0f / 256.0f);
        float ty = (float)((I >> 8)  + 1) * (1.0f / 256.0f);
        float dx = tx - px, dy = ty - py;
        float ed = sqrtf(dx * dx + dy * dy);

        #pragma unroll
        for (int o = 16; o > 0; o >>= 1) ed += __shfl_down_sync(FULL, ed, o);
        if (lane == 0) sh_ed[wid] = ed;
        __syncthreads();
        if (wid == 0) {
            ed = (lane < 8) ? sh_ed[lane] : 0.f;
            #pragma unroll
            for (int o = 4; o > 0; o >>= 1) ed += __shfl_down_sync(FULL, ed, o);
            if (lane == 0) {
                out[0] = ed * (1.0f / 32.0f);
                g_count = 0;               // reset for next graph replay
            }
        }
    }
}

extern "C" void kernel_launch(void* const* d_in, const int* in_sizes, int n_in,
                              void* d_out, int out_size) {
    const float* inp = (const float*)d_in[0];
    const float* tgt = (const float*)d_in[1];
    dsnt_l2pin_kernel<<<NBLK, NTHR>>>(inp, tgt, (float*)d_out);
}